// round 2
// baseline (speedup 1.0000x reference)
#include <cuda_runtime.h>
#include <cstdint>

#define N_NODES 20000
#define N_EDGES 500000

// padded dims
#define MP   20032   // 313*64 node rows
#define K1P  416     // zc width padded (400 -> 416)
#define ABW  832     // AB row stride: A in [0,416), B in [416,832)
#define N2P  208     // fc2 out padded (200 -> 208)
#define N3P  112     // fc3 out padded (100 -> 112)
#define TILE_E 128

// ---- scratch (static device globals; allocation-free) ----
__device__ float g_M[N_NODES * 16];
__device__ float g_ZC[MP * K1P];        // ~33 MB
__device__ float g_Wcat[K1P * ABW];     // fc1 split weights, tf32-rounded
__device__ float g_AB[MP * ABW];        // ~67 MB (L2-resident working set)
__device__ float g_W2p[K1P * N2P];      // fc2 weights padded, tf32
__device__ float g_W3p[N2P * N3P];      // fc3 weights padded, tf32

__device__ __forceinline__ float tf32r(float x) {
    asm("cvt.rna.tf32.f32 %0, %1;" : "=f"(x) : "f"(x));
    return x;
}

__device__ __forceinline__ void mma8(float c[4],
                                     uint32_t a0, uint32_t a1, uint32_t a2, uint32_t a3,
                                     uint32_t b0, uint32_t b1) {
    asm volatile(
        "mma.sync.aligned.m16n8k8.row.col.f32.tf32.tf32.f32 "
        "{%0,%1,%2,%3}, {%4,%5,%6,%7}, {%8,%9}, {%0,%1,%2,%3};"
        : "+f"(c[0]), "+f"(c[1]), "+f"(c[2]), "+f"(c[3])
        : "r"(a0), "r"(a1), "r"(a2), "r"(a3), "r"(b0), "r"(b1));
}

// ---- K0: build padded / tf32-rounded weight tables ----
__global__ void prep_weights(const float* __restrict__ fc1_w,
                             const float* __restrict__ fc2_w,
                             const float* __restrict__ fc3_w) {
    const int t1 = K1P * ABW, t2 = K1P * N2P, t3 = N2P * N3P;
    for (int i = blockIdx.x * blockDim.x + threadIdx.x; i < t1 + t2 + t3;
         i += gridDim.x * blockDim.x) {
        if (i < t1) {
            int k = i / ABW, j = i % ABW;
            float v = 0.f;
            if (k < 400) {
                if (j < 400) v = fc1_w[k * 400 + j];                       // W_top
                else if (j >= 416 && j < 816) v = fc1_w[(400 + k) * 400 + (j - 416)]; // W_bot
            }
            g_Wcat[i] = tf32r(v);
        } else if (i < t1 + t2) {
            int ii = i - t1;
            int k = ii / N2P, j = ii % N2P;
            float v = (k < 400 && j < 200) ? fc2_w[k * 200 + j] : 0.f;
            g_W2p[ii] = tf32r(v);
        } else {
            int ii = i - t1 - t2;
            int k = ii / N3P, j = ii % N3P;
            float v = (k < 200 && j < 100) ? fc3_w[k * 100 + j] : 0.f;
            g_W3p[ii] = tf32r(v);
        }
    }
}

// ---- K1: tiny per-node MLP 4->64->32->16 ----
__global__ void node_mlp(const float* __restrict__ cf,
                         const float* __restrict__ w1, const float* __restrict__ b1,
                         const float* __restrict__ w2, const float* __restrict__ b2,
                         const float* __restrict__ w3, const float* __restrict__ b3) {
    __shared__ float s_w1[4 * 64], s_b1[64], s_w2[64 * 32], s_b2[32], s_w3[32 * 16], s_b3[16];
    int tid = threadIdx.x;
    for (int i = tid; i < 256; i += blockDim.x)  s_w1[i] = w1[i];
    for (int i = tid; i < 64; i += blockDim.x)   s_b1[i] = b1[i];
    for (int i = tid; i < 2048; i += blockDim.x) s_w2[i] = w2[i];
    for (int i = tid; i < 32; i += blockDim.x)   s_b2[i] = b2[i];
    for (int i = tid; i < 512; i += blockDim.x)  s_w3[i] = w3[i];
    for (int i = tid; i < 16; i += blockDim.x)   s_b3[i] = b3[i];
    __syncthreads();
    int n = blockIdx.x * blockDim.x + tid;
    if (n >= N_NODES) return;
    float c0 = cf[n * 4], c1 = cf[n * 4 + 1], c2 = cf[n * 4 + 2], c3 = cf[n * 4 + 3];
    float h1[64];
#pragma unroll
    for (int j = 0; j < 64; j++) {
        float v = s_b1[j] + c0 * s_w1[j] + c1 * s_w1[64 + j] + c2 * s_w1[128 + j] + c3 * s_w1[192 + j];
        h1[j] = fmaxf(v, 0.f);
    }
    float h2[32];
    for (int j = 0; j < 32; j++) {
        float v = s_b2[j];
        for (int k = 0; k < 64; k++) v += h1[k] * s_w2[k * 32 + j];
        h2[j] = fmaxf(v, 0.f);
    }
    for (int j = 0; j < 16; j++) {
        float v = s_b3[j];
        for (int k = 0; k < 32; k++) v += h2[k] * s_w3[k * 16 + j];
        g_M[n * 16 + j] = v;
    }
}

// ---- K2: assemble padded zc = [z | m | esm | 0], tf32-rounded ----
__global__ void build_zc(const float* __restrict__ z, const float* __restrict__ esm) {
    const int total = MP * K1P;
    for (int i = blockIdx.x * blockDim.x + threadIdx.x; i < total;
         i += gridDim.x * blockDim.x) {
        int n = i / K1P, c = i % K1P;
        float v = 0.f;
        if (n < N_NODES) {
            if (c < 64) v = z[n * 64 + c];
            else if (c < 80) v = g_M[n * 16 + c - 64];
            else if (c < 400) v = esm[n * 320 + (c - 80)];
        }
        g_ZC[i] = tf32r(v);
    }
}

// ---- K3: AB = ZC @ Wcat  (tf32 mma, BM=64 BN=64 BK=32) ----
__global__ __launch_bounds__(256) void gemm_ab(const float* __restrict__ fc1_b) {
    __shared__ float As[64 * 33];
    __shared__ float Bs[32 * 65];
    int tid = threadIdx.x;
    int w = tid >> 5, lane = tid & 31;
    int g = lane >> 2, t = lane & 3;
    int wm = w & 3, wn = w >> 2;     // 4 m-groups x 2 n-halves
    int m0 = blockIdx.y * 64;
    int n0 = blockIdx.x * 64;
    float acc[4][4] = {};

    for (int kt = 0; kt < K1P; kt += 32) {
        for (int i = tid; i < 64 * 8; i += 256) {
            int r = i >> 3, c4 = (i & 7) * 4;
            float4 v = *(const float4*)&g_ZC[(m0 + r) * K1P + kt + c4];
            As[r * 33 + c4] = v.x; As[r * 33 + c4 + 1] = v.y;
            As[r * 33 + c4 + 2] = v.z; As[r * 33 + c4 + 3] = v.w;
        }
        for (int i = tid; i < 32 * 16; i += 256) {
            int r = i >> 4, c4 = (i & 15) * 4;
            float4 v = *(const float4*)&g_Wcat[(kt + r) * ABW + n0 + c4];
            Bs[r * 65 + c4] = v.x; Bs[r * 65 + c4 + 1] = v.y;
            Bs[r * 65 + c4 + 2] = v.z; Bs[r * 65 + c4 + 3] = v.w;
        }
        __syncthreads();
#pragma unroll
        for (int k8 = 0; k8 < 4; k8++) {
            int kk = k8 * 8;
            int ar = wm * 16 + g;
            uint32_t a0 = __float_as_uint(As[ar * 33 + kk + t]);
            uint32_t a1 = __float_as_uint(As[(ar + 8) * 33 + kk + t]);
            uint32_t a2 = __float_as_uint(As[ar * 33 + kk + t + 4]);
            uint32_t a3 = __float_as_uint(As[(ar + 8) * 33 + kk + t + 4]);
#pragma unroll
            for (int nf = 0; nf < 4; nf++) {
                int col = wn * 32 + nf * 8 + g;
                uint32_t b0 = __float_as_uint(Bs[(kk + t) * 65 + col]);
                uint32_t b1 = __float_as_uint(Bs[(kk + t + 4) * 65 + col]);
                mma8(acc[nf], a0, a1, a2, a3, b0, b1);
            }
        }
        __syncthreads();
    }
#pragma unroll
    for (int nf = 0; nf < 4; nf++) {
#pragma unroll
        for (int i = 0; i < 4; i++) {
            int r = m0 + wm * 16 + g + ((i >> 1) ? 8 : 0);
            int col = n0 + wn * 32 + nf * 8 + 2 * t + (i & 1);
            float v = acc[nf][i];
            if (col < 400) v += __ldg(&fc1_b[col]);   // fold b1 into A only
            g_AB[r * ABW + col] = v;
        }
    }
}

// ---- K4: fused edge kernel: gather+relu-add -> fc2 -> fc3 -> fc4 ----
__global__ __launch_bounds__(512, 1) void edge_kernel(
    const int* __restrict__ eidx,
    const float* __restrict__ b2, const float* __restrict__ b3,
    const float* __restrict__ w4, const float* __restrict__ b4v,
    float* __restrict__ out) {
    extern __shared__ float sm[];
    float* sh_h2 = sm;                        // 128*209
    float* sh_h3 = sh_h2 + 128 * 209;         // 128*113
    float* sh_h1 = sh_h3 + 128 * 113;         // 128*33
    float* sh_w  = sh_h1 + 128 * 33;          // 32*209 (reused as 16*113 in fc3)
    int* sh_src = (int*)(sh_w + 32 * 209);    // 128
    int* sh_dst = sh_src + 128;               // 128

    int tid = threadIdx.x;
    int w = tid >> 5, lane = tid & 31;
    int g = lane >> 2, t = lane & 3;
    int wm = w & 7;      // 8 row-groups of 16 edges
    int wn = w >> 3;     // 2 column halves
    int e0 = blockIdx.x * TILE_E;

    for (int i = tid; i < TILE_E; i += 512) {
        int e = e0 + i;
        int s = 0, d = 0;
        if (e < N_EDGES) {
            s = eidx[e];
            d = eidx[N_EDGES + e];
        }
        // clamp defensively: a bad index becomes a wrong (diagnosable) value,
        // not an illegal access
        s = min(max(s, 0), N_NODES - 1);
        d = min(max(d, 0), N_NODES - 1);
        sh_src[i] = s;
        sh_dst[i] = d;
    }
    __syncthreads();

    float acc2[13][4];
#pragma unroll
    for (int nf = 0; nf < 13; nf++)
#pragma unroll
        for (int i = 0; i < 4; i++) acc2[nf][i] = 0.f;

    // fc2: K = 416 (streamed), N = 208
    for (int kt = 0; kt < K1P; kt += 32) {
        {   // gather + relu-add h1 slice [128][32], 4 threads/edge
            int e = tid >> 2;
            int q = (tid & 3) * 8;
            int srow = sh_src[e], drow = sh_dst[e];
            float4 a0 = *(const float4*)&g_AB[(size_t)srow * ABW + kt + q];
            float4 a1 = *(const float4*)&g_AB[(size_t)srow * ABW + kt + q + 4];
            float4 bb0 = *(const float4*)&g_AB[(size_t)drow * ABW + 416 + kt + q];
            float4 bb1 = *(const float4*)&g_AB[(size_t)drow * ABW + 416 + kt + q + 4];
            float* p = &sh_h1[e * 33 + q];
            p[0] = tf32r(fmaxf(a0.x + bb0.x, 0.f)); p[1] = tf32r(fmaxf(a0.y + bb0.y, 0.f));
            p[2] = tf32r(fmaxf(a0.z + bb0.z, 0.f)); p[3] = tf32r(fmaxf(a0.w + bb0.w, 0.f));
            p[4] = tf32r(fmaxf(a1.x + bb1.x, 0.f)); p[5] = tf32r(fmaxf(a1.y + bb1.y, 0.f));
            p[6] = tf32r(fmaxf(a1.z + bb1.z, 0.f)); p[7] = tf32r(fmaxf(a1.w + bb1.w, 0.f));
        }
        for (int i = tid; i < 32 * 52; i += 512) {   // stage W2 slice [32][208]
            int r = i / 52, c4 = (i % 52) * 4;
            float4 v = *(const float4*)&g_W2p[(kt + r) * N2P + c4];
            float* p = &sh_w[r * 209 + c4];
            p[0] = v.x; p[1] = v.y; p[2] = v.z; p[3] = v.w;
        }
        __syncthreads();
#pragma unroll
        for (int k8 = 0; k8 < 4; k8++) {
            int kk = k8 * 8;
            int ar = wm * 16 + g;
            uint32_t a0 = __float_as_uint(sh_h1[ar * 33 + kk + t]);
            uint32_t a1 = __float_as_uint(sh_h1[(ar + 8) * 33 + kk + t]);
            uint32_t a2 = __float_as_uint(sh_h1[ar * 33 + kk + t + 4]);
            uint32_t a3 = __float_as_uint(sh_h1[(ar + 8) * 33 + kk + t + 4]);
#pragma unroll
            for (int nf = 0; nf < 13; nf++) {
                int col = wn * 104 + nf * 8 + g;
                uint32_t b0 = __float_as_uint(sh_w[(kk + t) * 209 + col]);
                uint32_t b1 = __float_as_uint(sh_w[(kk + t + 4) * 209 + col]);
                mma8(acc2[nf], a0, a1, a2, a3, b0, b1);
            }
        }
        __syncthreads();
    }
    // fc2 epilogue -> sh_h2 (relu + bias + tf32 round)
#pragma unroll
    for (int nf = 0; nf < 13; nf++) {
#pragma unroll
        for (int i = 0; i < 4; i++) {
            int r = wm * 16 + g + ((i >> 1) ? 8 : 0);
            int col = wn * 104 + nf * 8 + 2 * t + (i & 1);
            float v = acc2[nf][i];
            if (col < 200) v += __ldg(&b2[col]);
            sh_h2[r * 209 + col] = tf32r(fmaxf(v, 0.f));
        }
    }
    __syncthreads();

    // fc3: K = 208, N = 112
    float acc3[7][4];
#pragma unroll
    for (int nf = 0; nf < 7; nf++)
#pragma unroll
        for (int i = 0; i < 4; i++) acc3[nf][i] = 0.f;

    for (int kt = 0; kt < N2P; kt += 16) {
        for (int i = tid; i < 16 * 28; i += 512) {   // stage W3 slice [16][112]
            int r = i / 28, c4 = (i % 28) * 4;
            float4 v = *(const float4*)&g_W3p[(kt + r) * N3P + c4];
            float* p = &sh_w[r * 113 + c4];
            p[0] = v.x; p[1] = v.y; p[2] = v.z; p[3] = v.w;
        }
        __syncthreads();
#pragma unroll
        for (int k8 = 0; k8 < 2; k8++) {
            int kk = k8 * 8;
            int ar = wm * 16 + g;
            uint32_t a0 = __float_as_uint(sh_h2[ar * 209 + kt + kk + t]);
            uint32_t a1 = __float_as_uint(sh_h2[(ar + 8) * 209 + kt + kk + t]);
            uint32_t a2 = __float_as_uint(sh_h2[ar * 209 + kt + kk + t + 4]);
            uint32_t a3 = __float_as_uint(sh_h2[(ar + 8) * 209 + kt + kk + t + 4]);
#pragma unroll
            for (int nf = 0; nf < 7; nf++) {
                int col = wn * 56 + nf * 8 + g;
                uint32_t b0 = __float_as_uint(sh_w[(kk + t) * 113 + col]);
                uint32_t b1 = __float_as_uint(sh_w[(kk + t + 4) * 113 + col]);
                mma8(acc3[nf], a0, a1, a2, a3, b0, b1);
            }
        }
        __syncthreads();
    }
    // fc3 epilogue -> sh_h3
#pragma unroll
    for (int nf = 0; nf < 7; nf++) {
#pragma unroll
        for (int i = 0; i < 4; i++) {
            int r = wm * 16 + g + ((i >> 1) ? 8 : 0);
            int col = wn * 56 + nf * 8 + 2 * t + (i & 1);
            float v = acc3[nf][i];
            if (col < 100) v += __ldg(&b3[col]);
            sh_h3[r * 113 + col] = fmaxf(v, 0.f);
        }
    }
    __syncthreads();

    // fc4: dot(h3, w4) + b4, 4 threads per edge
    {
        int e = tid >> 2;
        int part = tid & 3;
        float s = 0.f;
#pragma unroll
        for (int c = 0; c < 25; c++) {
            int col = part * 25 + c;
            s += sh_h3[e * 113 + col] * __ldg(&w4[col]);
        }
        s += __shfl_xor_sync(0xffffffffu, s, 1);
        s += __shfl_xor_sync(0xffffffffu, s, 2);
        if (part == 0) {
            int eg = e0 + e;
            if (eg < N_EDGES) out[eg] = s + __ldg(&b4v[0]);
        }
    }
}

extern "C" void kernel_launch(void* const* d_in, const int* in_sizes, int n_in,
                              void* d_out, int out_size) {
    const float* z       = (const float*)d_in[0];
    const int*   ei      = (const int*)d_in[1];   // JAX default: int64 demoted to int32
    const float* cf      = (const float*)d_in[2];
    const float* esm     = (const float*)d_in[3];
    const float* mw1     = (const float*)d_in[4];
    const float* mb1     = (const float*)d_in[5];
    const float* mw2     = (const float*)d_in[6];
    const float* mb2     = (const float*)d_in[7];
    const float* mw3     = (const float*)d_in[8];
    const float* mb3     = (const float*)d_in[9];
    const float* fc1w    = (const float*)d_in[10];
    const float* fc1b    = (const float*)d_in[11];
    const float* fc2w    = (const float*)d_in[12];
    const float* fc2b    = (const float*)d_in[13];
    const float* fc3w    = (const float*)d_in[14];
    const float* fc3b    = (const float*)d_in[15];
    const float* fc4w    = (const float*)d_in[16];
    const float* fc4b    = (const float*)d_in[17];
    float* out = (float*)d_out;

    prep_weights<<<512, 256>>>(fc1w, fc2w, fc3w);
    node_mlp<<<(N_NODES + 127) / 128, 128>>>(cf, mw1, mb1, mw2, mb2, mw3, mb3);
    build_zc<<<2048, 256>>>(z, esm);
    gemm_ab<<<dim3(13, 313), 256>>>(fc1b);

    size_t smem = (size_t)(128 * 209 + 128 * 113 + 128 * 33 + 32 * 209) * sizeof(float)
                + 256 * sizeof(int);
    cudaFuncSetAttribute(edge_kernel, cudaFuncAttributeMaxDynamicSharedMemorySize, (int)smem);
    edge_kernel<<<(N_EDGES + TILE_E - 1) / TILE_E, 512, smem>>>(ei, fc2b, fc3b, fc4w, fc4b, out);
}

// round 4
// speedup vs baseline: 1.7105x; 1.7105x over previous
#include <cuda_runtime.h>
#include <cstdint>

#define N_NODES 20000
#define N_EDGES 500000

// padded dims
#define MP   20032   // node rows padded
#define K1P  416     // zc width padded (400 -> 416)
#define ABW  832     // AB row stride: A in [0,416), B in [416,832)
#define N2P  224     // fc2 out padded (200 -> 224), 28 n8-tiles
#define N3P  128     // fc3 out padded (100 -> 128), 16 n8-tiles
#define TILE_E 128

// fragment-layout table sizes
#define W2F_TOTAL (13 * 4 * 28 * 64)   // 93184 floats
#define W3F_TOTAL (7 * 4 * 16 * 64)    // 28672 floats

// ---- scratch (static device globals; allocation-free) ----
__device__ float g_M[N_NODES * 16];
__device__ __align__(16) float g_ZC[MP * K1P];
__device__ __align__(16) float g_Wcat[K1P * ABW];
__device__ __align__(16) float g_AB[MP * ABW];       // ~67 MB, L2-resident
__device__ __align__(16) float g_W2f[W2F_TOTAL];     // fc2 weights, mma-fragment order
__device__ __align__(16) float g_W3f[W3F_TOTAL];     // fc3 weights, mma-fragment order

__device__ __forceinline__ float tf32r(float x) {
    asm("cvt.rna.tf32.f32 %0, %1;" : "=f"(x) : "f"(x));
    return x;
}

__device__ __forceinline__ void mma8(float c[4],
                                     uint32_t a0, uint32_t a1, uint32_t a2, uint32_t a3,
                                     uint32_t b0, uint32_t b1) {
    asm volatile(
        "mma.sync.aligned.m16n8k8.row.col.f32.tf32.tf32.f32 "
        "{%0,%1,%2,%3}, {%4,%5,%6,%7}, {%8,%9}, {%0,%1,%2,%3};"
        : "+f"(c[0]), "+f"(c[1]), "+f"(c[2]), "+f"(c[3])
        : "r"(a0), "r"(a1), "r"(a2), "r"(a3), "r"(b0), "r"(b1));
}

// ---- K0: build weight tables (Wcat for gemm_ab, W2f/W3f in fragment order) ----
__global__ void prep_weights(const float* __restrict__ fc1_w,
                             const float* __restrict__ fc2_w,
                             const float* __restrict__ fc3_w) {
    const int t1 = K1P * ABW, t2 = W2F_TOTAL, t3 = W3F_TOTAL;
    for (int i = blockIdx.x * blockDim.x + threadIdx.x; i < t1 + t2 + t3;
         i += gridDim.x * blockDim.x) {
        if (i < t1) {
            int k = i / ABW, j = i % ABW;
            float v = 0.f;
            if (k < 400) {
                if (j < 400) v = fc1_w[k * 400 + j];
                else if (j >= 416 && j < 816) v = fc1_w[(400 + k) * 400 + (j - 416)];
            }
            g_Wcat[i] = tf32r(v);
        } else if (i < t1 + t2) {
            // W2f layout: ((kt*4 + k8)*28 + nf)*64 + lane*2 + p
            int ii = i - t1;
            int p = ii & 1, lane = (ii >> 1) & 31;
            int r = ii >> 6;
            int nf = r % 28, k8 = (r / 28) & 3, kt = r / 112;
            int g = lane >> 2, t = lane & 3;
            int k = kt * 32 + k8 * 8 + t + 4 * p;
            int col = nf * 8 + g;
            float v = (k < 400 && col < 200) ? fc2_w[k * 200 + col] : 0.f;
            g_W2f[ii] = tf32r(v);
        } else {
            // W3f layout: ((kt3*4 + k8)*16 + nf)*64 + lane*2 + p ; K over 224, N over 128
            int ii = i - t1 - t2;
            int p = ii & 1, lane = (ii >> 1) & 31;
            int r = ii >> 6;
            int nf = r % 16, k8 = (r / 16) & 3, kt3 = r / 64;
            int g = lane >> 2, t = lane & 3;
            int k = kt3 * 32 + k8 * 8 + t + 4 * p;
            int col = nf * 8 + g;
            float v = (k < 200 && col < 100) ? fc3_w[k * 100 + col] : 0.f;
            g_W3f[ii] = tf32r(v);
        }
    }
}

// ---- K1: tiny per-node MLP 4->64->32->16 ----
__global__ void node_mlp(const float* __restrict__ cf,
                         const float* __restrict__ w1, const float* __restrict__ b1,
                         const float* __restrict__ w2, const float* __restrict__ b2,
                         const float* __restrict__ w3, const float* __restrict__ b3) {
    __shared__ float s_w1[4 * 64], s_b1[64], s_w2[64 * 32], s_b2[32], s_w3[32 * 16], s_b3[16];
    int tid = threadIdx.x;
    for (int i = tid; i < 256; i += blockDim.x)  s_w1[i] = w1[i];
    for (int i = tid; i < 64; i += blockDim.x)   s_b1[i] = b1[i];
    for (int i = tid; i < 2048; i += blockDim.x) s_w2[i] = w2[i];
    for (int i = tid; i < 32; i += blockDim.x)   s_b2[i] = b2[i];
    for (int i = tid; i < 512; i += blockDim.x)  s_w3[i] = w3[i];
    for (int i = tid; i < 16; i += blockDim.x)   s_b3[i] = b3[i];
    __syncthreads();
    int n = blockIdx.x * blockDim.x + tid;
    if (n >= N_NODES) return;
    float c0 = cf[n * 4], c1 = cf[n * 4 + 1], c2 = cf[n * 4 + 2], c3 = cf[n * 4 + 3];
    float h1[64];
#pragma unroll
    for (int j = 0; j < 64; j++) {
        float v = s_b1[j] + c0 * s_w1[j] + c1 * s_w1[64 + j] + c2 * s_w1[128 + j] + c3 * s_w1[192 + j];
        h1[j] = fmaxf(v, 0.f);
    }
    float h2[32];
    for (int j = 0; j < 32; j++) {
        float v = s_b2[j];
        for (int k = 0; k < 64; k++) v += h1[k] * s_w2[k * 32 + j];
        h2[j] = fmaxf(v, 0.f);
    }
    for (int j = 0; j < 16; j++) {
        float v = s_b3[j];
        for (int k = 0; k < 32; k++) v += h2[k] * s_w3[k * 16 + j];
        g_M[n * 16 + j] = v;
    }
}

// ---- K2: assemble padded zc = [z | m | esm | 0], tf32-rounded ----
__global__ void build_zc(const float* __restrict__ z, const float* __restrict__ esm) {
    const int total = MP * K1P;
    for (int i = blockIdx.x * blockDim.x + threadIdx.x; i < total;
         i += gridDim.x * blockDim.x) {
        int n = i / K1P, c = i % K1P;
        float v = 0.f;
        if (n < N_NODES) {
            if (c < 64) v = z[n * 64 + c];
            else if (c < 80) v = g_M[n * 16 + c - 64];
            else if (c < 400) v = esm[n * 320 + (c - 80)];
        }
        g_ZC[i] = tf32r(v);
    }
}

// ---- K3: AB = ZC @ Wcat  (tf32 mma, BM=64 BN=64 BK=32; conflict-free strides) ----
__global__ __launch_bounds__(256) void gemm_ab(const float* __restrict__ fc1_b) {
    __shared__ float As[64 * 36];   // stride 36: (36g+t) mod 32 = 4g+t, distinct
    __shared__ float Bs[32 * 72];   // stride 72: (72t+g) mod 32 = 8t+g, distinct
    int tid = threadIdx.x;
    int w = tid >> 5, lane = tid & 31;
    int g = lane >> 2, t = lane & 3;
    int wm = w & 3, wn = w >> 2;
    int m0 = blockIdx.y * 64;
    int n0 = blockIdx.x * 64;
    float acc[4][4] = {};

    for (int kt = 0; kt < K1P; kt += 32) {
        for (int i = tid; i < 64 * 8; i += 256) {
            int r = i >> 3, c4 = (i & 7) * 4;
            float4 v = *(const float4*)&g_ZC[(m0 + r) * K1P + kt + c4];
            As[r * 36 + c4] = v.x; As[r * 36 + c4 + 1] = v.y;
            As[r * 36 + c4 + 2] = v.z; As[r * 36 + c4 + 3] = v.w;
        }
        for (int i = tid; i < 32 * 16; i += 256) {
            int r = i >> 4, c4 = (i & 15) * 4;
            float4 v = *(const float4*)&g_Wcat[(kt + r) * ABW + n0 + c4];
            Bs[r * 72 + c4] = v.x; Bs[r * 72 + c4 + 1] = v.y;
            Bs[r * 72 + c4 + 2] = v.z; Bs[r * 72 + c4 + 3] = v.w;
        }
        __syncthreads();
#pragma unroll
        for (int k8 = 0; k8 < 4; k8++) {
            int kk = k8 * 8;
            int ar = wm * 16 + g;
            uint32_t a0 = __float_as_uint(As[ar * 36 + kk + t]);
            uint32_t a1 = __float_as_uint(As[(ar + 8) * 36 + kk + t]);
            uint32_t a2 = __float_as_uint(As[ar * 36 + kk + t + 4]);
            uint32_t a3 = __float_as_uint(As[(ar + 8) * 36 + kk + t + 4]);
#pragma unroll
            for (int nf = 0; nf < 4; nf++) {
                int col = wn * 32 + nf * 8 + g;
                uint32_t b0 = __float_as_uint(Bs[(kk + t) * 72 + col]);
                uint32_t b1 = __float_as_uint(Bs[(kk + t + 4) * 72 + col]);
                mma8(acc[nf], a0, a1, a2, a3, b0, b1);
            }
        }
        __syncthreads();
    }
#pragma unroll
    for (int nf = 0; nf < 4; nf++) {
#pragma unroll
        for (int i = 0; i < 4; i++) {
            int r = m0 + wm * 16 + g + ((i >> 1) ? 8 : 0);
            int col = n0 + wn * 32 + nf * 8 + 2 * t + (i & 1);
            float v = acc[nf][i];
            if (col < 400) v += __ldg(&fc1_b[col]);   // fold b1 into A half only
            g_AB[r * ABW + col] = v;
        }
    }
}

// ============================================================================
// K4: fused edge kernel, fragment-layout smem, 4m x 4n warp tiling
//   smem word map:
//     h2f   [0, 29568)       : 224 blocks of 132  (fc3 A operand, frag order)
//     h1f   [29568, 33792)   : 32 blocks of 132   (fc2 A operand, frag order)
//     wbuf  [33792, 40960)   : 7168 (fc2 W slice) / 4096 (fc3 W slice)
//     spart [40960, 41472)   : fc4 partials [4][128]
//     sw4   [41472, 41600)   : padded w4
//     ssrc  [41600, 41728)   : src indices (int)
//     sdst  [41728, 41856)   : dst indices (int)
// ============================================================================
#define SM_H2F   0
#define SM_H1F   29568
#define SM_WBUF  33792
#define SM_SPART 40960
#define SM_SW4   41472
#define SM_SRC   41600
#define SM_DST   41728
#define SM_WORDS 41856

__global__ __launch_bounds__(512, 1) void edge_kernel(
    const int* __restrict__ eidx,
    const float* __restrict__ b2, const float* __restrict__ b3,
    const float* __restrict__ w4, const float* __restrict__ b4v,
    float* __restrict__ out) {
    extern __shared__ float sm[];
    float* h2f = sm + SM_H2F;
    float* h1f = sm + SM_H1F;
    float* wbuf = sm + SM_WBUF;
    float* spart = sm + SM_SPART;
    float* sw4 = sm + SM_SW4;
    int* ssrc = (int*)(sm + SM_SRC);
    int* sdst = (int*)(sm + SM_DST);

    int tid = threadIdx.x;
    int w = tid >> 5, lane = tid & 31;
    int g = lane >> 2, t = lane & 3;
    int wm = w & 3, wn = w >> 2;   // 4 m-warps (32 rows each) x 4 n-warps
    int e0 = blockIdx.x * TILE_E;

    if (tid < TILE_E) {
        int e = e0 + tid;
        int s = 0, d = 0;
        if (e < N_EDGES) { s = eidx[e]; d = eidx[N_EDGES + e]; }
        s = min(max(s, 0), N_NODES - 1);
        d = min(max(d, 0), N_NODES - 1);
        ssrc[tid] = s; sdst[tid] = d;
        sw4[tid] = (tid < 100) ? __ldg(&w4[tid]) : 0.f;
    }
    __syncthreads();

    // gather-thread geometry: each thread owns (edge ge, k8 slice k8g)
    int ge = tid >> 2;
    int k8g = tid & 3;
    int gg = ge & 7, rpg = (ge >> 3) & 1, mtg_g = ge >> 4;
    float* h1w = &h1f[(mtg_g * 4 + k8g) * 132 + gg * 16 + rpg];
    const float* srowp = &g_AB[(size_t)ssrc[ge] * ABW];
    const float* drowp = &g_AB[(size_t)sdst[ge] * ABW + 416];

    float acc2[2][7][4] = {};

    // ---------------- fc2: K=416 (13 ktiles of 32), N=224 ----------------
    for (int kt = 0; kt < K1P; kt += 32) {
        {   // stage h1 fragment tile [128][32]
            int q = k8g * 8;
            float4 a0 = *(const float4*)&srowp[kt + q];
            float4 a1 = *(const float4*)&srowp[kt + q + 4];
            float4 c0 = *(const float4*)&drowp[kt + q];
            float4 c1 = *(const float4*)&drowp[kt + q + 4];
            h1w[0]  = tf32r(fmaxf(a0.x + c0.x, 0.f));
            h1w[4]  = tf32r(fmaxf(a0.y + c0.y, 0.f));
            h1w[8]  = tf32r(fmaxf(a0.z + c0.z, 0.f));
            h1w[12] = tf32r(fmaxf(a0.w + c0.w, 0.f));
            h1w[2]  = tf32r(fmaxf(a1.x + c1.x, 0.f));
            h1w[6]  = tf32r(fmaxf(a1.y + c1.y, 0.f));
            h1w[10] = tf32r(fmaxf(a1.z + c1.z, 0.f));
            h1w[14] = tf32r(fmaxf(a1.w + c1.w, 0.f));
        }
        {   // stage W2 fragment slice: 7168 floats = 1792 float4
            const float4* src4 = (const float4*)&g_W2f[(kt >> 5) * 7168];
            float4* dst4 = (float4*)wbuf;
            dst4[tid] = src4[tid];
            dst4[tid + 512] = src4[tid + 512];
            dst4[tid + 1024] = src4[tid + 1024];
            if (tid < 256) dst4[tid + 1536] = src4[tid + 1536];
        }
        __syncthreads();
#pragma unroll
        for (int k8 = 0; k8 < 4; k8++) {
            float4 af0 = *(const float4*)&h1f[((wm * 2 + 0) * 4 + k8) * 132 + lane * 4];
            float4 af1 = *(const float4*)&h1f[((wm * 2 + 1) * 4 + k8) * 132 + lane * 4];
            uint32_t a00 = __float_as_uint(af0.x), a01 = __float_as_uint(af0.y);
            uint32_t a02 = __float_as_uint(af0.z), a03 = __float_as_uint(af0.w);
            uint32_t a10 = __float_as_uint(af1.x), a11 = __float_as_uint(af1.y);
            uint32_t a12 = __float_as_uint(af1.z), a13 = __float_as_uint(af1.w);
#pragma unroll
            for (int nf = 0; nf < 7; nf++) {
                float2 bf = *(const float2*)&wbuf[((k8 * 28 + wn * 7 + nf) * 32 + lane) * 2];
                uint32_t b0 = __float_as_uint(bf.x), b1 = __float_as_uint(bf.y);
                mma8(acc2[0][nf], a00, a01, a02, a03, b0, b1);
                mma8(acc2[1][nf], a10, a11, a12, a13, b0, b1);
            }
        }
        __syncthreads();
    }

    // fc2 epilogue: bias + relu + tf32-round, scatter into h2f (fc3 A-fragment order)
#pragma unroll
    for (int mt = 0; mt < 2; mt++) {
        int mtg = wm * 2 + mt;
#pragma unroll
        for (int nf = 0; nf < 7; nf++) {
            int kg = wn * 7 + nf;
            float* base = &h2f[(mtg * 28 + kg) * 132];
#pragma unroll
            for (int i = 0; i < 4; i++) {
                int colp = 2 * t + (i & 1);           // 0..7 within n8-tile
                int col = wn * 56 + nf * 8 + colp;
                float v = acc2[mt][nf][i];
                if (col < 200) v += __ldg(&b2[col]);
                v = tf32r(fmaxf(v, 0.f));
                int lanep = g * 4 + (colp & 3);
                int comp = (i >> 1) + 2 * (colp >> 2);
                base[lanep * 4 + comp] = v;
            }
        }
    }
    __syncthreads();

    // ---------------- fc3: K=224 (7 ktiles of 32), N=128 ----------------
    float acc3[2][4][4] = {};
    for (int kt3 = 0; kt3 < 7; kt3++) {
        {   // stage W3 fragment slice: 4096 floats = 1024 float4
            const float4* src4 = (const float4*)&g_W3f[kt3 * 4096];
            float4* dst4 = (float4*)wbuf;
            dst4[tid] = src4[tid];
            dst4[tid + 512] = src4[tid + 512];
        }
        __syncthreads();
#pragma unroll
        for (int k8 = 0; k8 < 4; k8++) {
            int kg = kt3 * 4 + k8;
            float4 af0 = *(const float4*)&h2f[((wm * 2 + 0) * 28 + kg) * 132 + lane * 4];
            float4 af1 = *(const float4*)&h2f[((wm * 2 + 1) * 28 + kg) * 132 + lane * 4];
            uint32_t a00 = __float_as_uint(af0.x), a01 = __float_as_uint(af0.y);
            uint32_t a02 = __float_as_uint(af0.z), a03 = __float_as_uint(af0.w);
            uint32_t a10 = __float_as_uint(af1.x), a11 = __float_as_uint(af1.y);
            uint32_t a12 = __float_as_uint(af1.z), a13 = __float_as_uint(af1.w);
#pragma unroll
            for (int nf = 0; nf < 4; nf++) {
                float2 bf = *(const float2*)&wbuf[((k8 * 16 + wn * 4 + nf) * 32 + lane) * 2];
                uint32_t b0 = __float_as_uint(bf.x), b1 = __float_as_uint(bf.y);
                mma8(acc3[0][nf], a00, a01, a02, a03, b0, b1);
                mma8(acc3[1][nf], a10, a11, a12, a13, b0, b1);
            }
        }
        __syncthreads();
    }

    // ---------------- fc3 epilogue + fc4 dot ----------------
    float s2[2][2] = {};
#pragma unroll
    for (int mt = 0; mt < 2; mt++) {
#pragma unroll
        for (int nf = 0; nf < 4; nf++) {
#pragma unroll
            for (int i = 0; i < 4; i++) {
                int col = wn * 32 + nf * 8 + 2 * t + (i & 1);
                float v = acc3[mt][nf][i];
                if (col < 100) v += __ldg(&b3[col]);
                v = fmaxf(v, 0.f);
                s2[mt][i >> 1] += v * sw4[col];
            }
        }
    }
#pragma unroll
    for (int mt = 0; mt < 2; mt++) {
#pragma unroll
        for (int rp = 0; rp < 2; rp++) {
            float v = s2[mt][rp];
            v += __shfl_xor_sync(0xffffffffu, v, 1);
            v += __shfl_xor_sync(0xffffffffu, v, 2);
            if (t == 0) spart[wn * 128 + wm * 32 + mt * 16 + g + 8 * rp] = v;
        }
    }
    __syncthreads();
    if (tid < TILE_E) {
        float v = spart[tid] + spart[128 + tid] + spart[256 + tid] + spart[384 + tid]
                + __ldg(&b4v[0]);
        int e = e0 + tid;
        if (e < N_EDGES) out[e] = v;
    }
}

extern "C" void kernel_launch(void* const* d_in, const int* in_sizes, int n_in,
                              void* d_out, int out_size) {
    const float* z       = (const float*)d_in[0];
    const int*   ei      = (const int*)d_in[1];
    const float* cf      = (const float*)d_in[2];
    const float* esm     = (const float*)d_in[3];
    const float* mw1     = (const float*)d_in[4];
    const float* mb1     = (const float*)d_in[5];
    const float* mw2     = (const float*)d_in[6];
    const float* mb2     = (const float*)d_in[7];
    const float* mw3     = (const float*)d_in[8];
    const float* mb3     = (const float*)d_in[9];
    const float* fc1w    = (const float*)d_in[10];
    const float* fc1b    = (const float*)d_in[11];
    const float* fc2w    = (const float*)d_in[12];
    const float* fc2b    = (const float*)d_in[13];
    const float* fc3w    = (const float*)d_in[14];
    const float* fc3b    = (const float*)d_in[15];
    const float* fc4w    = (const float*)d_in[16];
    const float* fc4b    = (const float*)d_in[17];
    float* out = (float*)d_out;

    prep_weights<<<512, 256>>>(fc1w, fc2w, fc3w);
    node_mlp<<<(N_NODES + 127) / 128, 128>>>(cf, mw1, mb1, mw2, mb2, mw3, mb3);
    build_zc<<<2048, 256>>>(z, esm);
    gemm_ab<<<dim3(13, 313), 256>>>(fc1b);

    size_t smem = (size_t)SM_WORDS * sizeof(float);   // 167424 bytes
    cudaFuncSetAttribute(edge_kernel, cudaFuncAttributeMaxDynamicSharedMemorySize, (int)smem);
    edge_kernel<<<(N_EDGES + TILE_E - 1) / TILE_E, 512, smem>>>(ei, fc2b, fc3b, fc4w, fc4b, out);
}